// round 16
// baseline (speedup 1.0000x reference)
#include <cuda_runtime.h>
#include <cuda_bf16.h>
#include <cstdint>

#define N_NODES 50000
#define N_EDGES 800000
#define IN_DIM  256
#define HID_DIM 256
#define OUT_DIM 128

#define TOTN (2 * N_NODES)   // combined node slots (both graphs)
#define TOTE (2 * N_EDGES)   // combined edges

// half split (in 128-row M tiles): H0 = 391 tiles = 50048 nodes
#define H0_TILES 391
#define H0_NODES (H0_TILES * 128)        // 50048
#define H1_TILES 391                     // covers remaining 49952 (clamped)
#define H1_NODES (TOTN - H0_NODES)       // 49952

// ---------------------------------------------------------------------------
// Device scratch (no runtime allocation allowed) — combined for both graphs
// ---------------------------------------------------------------------------
__device__ __align__(128) __nv_bfloat16 g_xs  [TOTN * 512];  // x split: [hi(256) | lo(256)]
__device__ __align__(128) __nv_bfloat16 g_aggs[TOTN * 512];  // agg split: [hi | lo]
__device__ __align__(128) float         g_h1  [TOTN * HID_DIM];
__device__ __align__(128) float         g_h2  [TOTN * OUT_DIM];
__device__ __align__(128) __nv_bfloat16 g_w1hi[HID_DIM * 256];  // [N=256][K=256] K-major
__device__ __align__(128) __nv_bfloat16 g_w1lo[HID_DIM * 256];
__device__ __align__(128) __nv_bfloat16 g_w2hi[OUT_DIM * 256];  // [N=128][K=256]
__device__ __align__(128) __nv_bfloat16 g_w2lo[OUT_DIM * 256];
__device__ float g_dinv[TOTN];
__device__ int   g_count[TOTN];
__device__ int   g_row  [TOTN + 1];
__device__ int   g_cur  [TOTN];
__device__ int   g_esrc [TOTE];      // GLOBAL source ids (graph2 offset by N_NODES)

// decomposed-scan block sums
#define SBS 1024
#define SNB ((TOTN + SBS - 1) / SBS)   // 98
__device__ int g_bsum[SNB];

// ---------------------------------------------------------------------------
// PTX helpers (all legal at base sm_103 target)
// ---------------------------------------------------------------------------
__device__ __forceinline__ uint32_t s2u(const void* p) {
    uint32_t a;
    asm("{ .reg .u64 t; cvta.to.shared.u64 t, %1; cvt.u32.u64 %0, t; }"
        : "=r"(a) : "l"(p));
    return a;
}
__device__ __forceinline__ void cp_async16(uint32_t dst, const void* src) {
    asm volatile("cp.async.cg.shared.global [%0], [%1], 16;" :: "r"(dst), "l"(src));
}
#define CP_COMMIT() asm volatile("cp.async.commit_group;" ::: "memory")
#define CP_WAIT(n)  asm volatile("cp.async.wait_group %0;" :: "n"(n) : "memory")

#define LDMX4(r0, r1, r2, r3, addr) \
    asm volatile("ldmatrix.sync.aligned.m8n8.x4.shared.b16 {%0,%1,%2,%3}, [%4];" \
                 : "=r"(r0), "=r"(r1), "=r"(r2), "=r"(r3) : "r"(addr))

#define MMA16816(d, a, b) \
    asm volatile("mma.sync.aligned.m16n8k16.row.col.f32.bf16.bf16.f32 " \
                 "{%0,%1,%2,%3}, {%4,%5,%6,%7}, {%8,%9}, {%0,%1,%2,%3};" \
                 : "+f"((d)[0]), "+f"((d)[1]), "+f"((d)[2]), "+f"((d)[3]) \
                 : "r"((a)[0]), "r"((a)[1]), "r"((a)[2]), "r"((a)[3]), \
                   "r"((b)[0]), "r"((b)[1]))

// ---------------------------------------------------------------------------
// CSR build (both graphs combined)
// ---------------------------------------------------------------------------
__global__ void k_hist2(const int* __restrict__ dst1, const int* __restrict__ dst2,
                        int* __restrict__ count) {
    int e = blockIdx.x * blockDim.x + threadIdx.x;
    if (e >= TOTE) return;
    int slot = (e < N_EDGES) ? dst1[e] : (dst2[e - N_EDGES] + N_NODES);
    atomicAdd(&count[slot], 1);
}

__global__ __launch_bounds__(SBS)
void k_scan_a(const int* __restrict__ count, int* __restrict__ bsum) {
    __shared__ int sh[SBS / 32];
    int i = blockIdx.x * SBS + threadIdx.x;
    int v = (i < TOTN) ? count[i] : 0;
#pragma unroll
    for (int off = 16; off > 0; off >>= 1)
        v += __shfl_down_sync(0xffffffff, v, off);
    if ((threadIdx.x & 31) == 0) sh[threadIdx.x >> 5] = v;
    __syncthreads();
    if (threadIdx.x < SBS / 32) {
        int s = sh[threadIdx.x];
#pragma unroll
        for (int off = SBS / 64; off > 0; off >>= 1)
            s += __shfl_down_sync(0xffffffff, s, off, SBS / 32);
        if (threadIdx.x == 0) bsum[blockIdx.x] = s;
    }
}

__global__ __launch_bounds__(128)
void k_scan_b(int* __restrict__ bsum) {
    __shared__ int sh[128];
    int tid = threadIdx.x;
    int v = (tid < SNB) ? bsum[tid] : 0;
    sh[tid] = v;
    __syncthreads();
    for (int off = 1; off < 128; off <<= 1) {
        int t = 0;
        if (tid >= off) t = sh[tid - off];
        __syncthreads();
        if (tid >= off) sh[tid] += t;
        __syncthreads();
    }
    if (tid < SNB) bsum[tid] = sh[tid] - v;   // exclusive
}

__global__ __launch_bounds__(SBS)
void k_scan_c(const int* __restrict__ count, const int* __restrict__ bsum,
              int* __restrict__ row, int* __restrict__ cur,
              float* __restrict__ dinv) {
    __shared__ int sh[SBS];
    int tid = threadIdx.x;
    int i = blockIdx.x * SBS + tid;
    int v = (i < TOTN) ? count[i] : 0;
    sh[tid] = v;
    __syncthreads();
    for (int off = 1; off < SBS; off <<= 1) {
        int t = 0;
        if (tid >= off) t = sh[tid - off];
        __syncthreads();
        if (tid >= off) sh[tid] += t;
        __syncthreads();
    }
    if (i < TOTN) {
        int excl = sh[tid] - v + bsum[blockIdx.x];
        row[i] = excl;
        cur[i] = excl;
        dinv[i] = rsqrtf((float)v + 1.0f);
        if (i == TOTN - 1) row[TOTN] = excl + v;
    }
}

__global__ void k_scatter2(const int* __restrict__ src1, const int* __restrict__ dst1,
                           const int* __restrict__ src2, const int* __restrict__ dst2,
                           int* __restrict__ cur, int* __restrict__ esrc) {
    int e = blockIdx.x * blockDim.x + threadIdx.x;
    if (e >= TOTE) return;
    int s, slot;
    if (e < N_EDGES) { s = src1[e];            slot = dst1[e]; }
    else             { s = src2[e - N_EDGES] + N_NODES;
                       slot = dst2[e - N_EDGES] + N_NODES; }
    int pos = atomicAdd(&cur[slot], 1);
    esrc[pos] = s;   // GLOBAL node id
}

// ---------------------------------------------------------------------------
// fp32 -> (hi, lo) bf16 split helpers & conversion kernels
// ---------------------------------------------------------------------------
__device__ __forceinline__ void split_store4(__nv_bfloat16* hp, __nv_bfloat16* lp, float4 v) {
    __nv_bfloat162 h01 = __floats2bfloat162_rn(v.x, v.y);
    __nv_bfloat162 h23 = __floats2bfloat162_rn(v.z, v.w);
    float2 f01 = __bfloat1622float2(h01);
    float2 f23 = __bfloat1622float2(h23);
    __nv_bfloat162 l01 = __floats2bfloat162_rn(v.x - f01.x, v.y - f01.y);
    __nv_bfloat162 l23 = __floats2bfloat162_rn(v.z - f23.x, v.w - f23.y);
    ((__nv_bfloat162*)hp)[0] = h01;
    ((__nv_bfloat162*)hp)[1] = h23;
    ((__nv_bfloat162*)lp)[0] = l01;
    ((__nv_bfloat162*)lp)[1] = l23;
}

// node range [base, base+cnt) of combined x -> xs
__global__ void k_cvt_x2(const float* __restrict__ x1, const float* __restrict__ x2,
                         __nv_bfloat16* __restrict__ xs, int base, int cnt) {
    int idx = blockIdx.x * blockDim.x + threadIdx.x;  // float4 index within range
    if (idx >= cnt * 64) return;
    int node = base + (idx >> 6);
    int f4   = idx & 63;
    const float4* src = (node < N_NODES)
        ? (const float4*)x1 + ((size_t)node * 64 + f4)
        : (const float4*)x2 + ((size_t)(node - N_NODES) * 64 + f4);
    float4 v = *src;
    split_store4(xs + (size_t)node * 512 + f4 * 4,
                 xs + (size_t)node * 512 + 256 + f4 * 4, v);
}

// W [K=256, N] row-major fp32 -> hi/lo [N, 256] K-major bf16 (transposed)
__global__ void k_cvt_w(const float* __restrict__ W, __nv_bfloat16* __restrict__ hi,
                        __nv_bfloat16* __restrict__ lo, int N) {
    int idx = blockIdx.x * blockDim.x + threadIdx.x;
    if (idx >= 256 * N) return;
    int n = idx / 256;
    int k = idx % 256;
    float v = W[(size_t)k * N + n];
    __nv_bfloat16 h = __float2bfloat16(v);
    hi[(size_t)n * 256 + k] = h;
    lo[(size_t)n * 256 + k] = __float2bfloat16(v - __bfloat162float(h));
}

// ---------------------------------------------------------------------------
// mma.sync bf16x3 GEMM:
//   8 K32-chunks; each chunk loads 4 tiles (Ahi, Alo, Bhi, Blo) and performs
//   all 3 split passes (Ahi*Bhi + Alo*Bhi + Ahi*Blo) with ldmatrix fragments.
// CTA: 128(M) x 128(N), 8 warps in 4(M) x 2(N); warp tile 32x64.
// mtile_base: M-tile offset (for half-split launches).
// ---------------------------------------------------------------------------
#define SLDA 40                       // smem row stride (bf16): 32 data + 8 pad
#define TILE_E (128 * SLDA)           // elements per tile
#define TILE_B (TILE_E * 2)           // bytes per tile (10240)
#define GSMEM  (8 * TILE_B)           // 2 buffers x 4 tiles = 81920 bytes

template <int NC>
__global__ __launch_bounds__(256)
void k_mma_gemm(const __nv_bfloat16* __restrict__ A,
                const __nv_bfloat16* __restrict__ Bhi,
                const __nv_bfloat16* __restrict__ Blo,
                float* __restrict__ C, int M, int mtile_base) {
    extern __shared__ __align__(16) __nv_bfloat16 smem[];
    const uint32_t sbase = s2u(smem);

    const int tid  = threadIdx.x;
    const int wid  = tid >> 5;
    const int lane = tid & 31;
    const int wm   = wid & 3;        // warp M index (0..3) -> 32 rows
    const int wn   = wid >> 2;       // warp N index (0..1) -> 64 cols
    const int m0   = (mtile_base + blockIdx.x) * 128;
    const int n0   = blockIdx.y * 128;
    const int g    = lane >> 2;      // mma group row
    const int t    = lane & 3;       // mma thread col

    const int a_row_l = lane & 15;
    const int a_col_l = (lane >> 4) * 8;
    const int g8      = lane >> 3;
    const int b_row_l = (lane & 7) + 8 * (g8 >> 1);
    const int b_col_l = 8 * (g8 & 1);

    float acc[2][8][4];
#pragma unroll
    for (int i = 0; i < 2; ++i)
#pragma unroll
        for (int j = 0; j < 8; ++j)
#pragma unroll
            for (int q = 0; q < 4; ++q) acc[i][j][q] = 0.0f;

    auto load_chunk = [&](int c, int buf) {
        const int kc = c * 32;
        const uint32_t sb = sbase + buf * 4 * TILE_B;
#pragma unroll
        for (int it = 0; it < 2; ++it) {
            int idx = it * 256 + tid;
            int r = idx >> 2, cl = idx & 3;
            uint32_t doff = (r * SLDA + cl * 8) * 2;
            if (m0 + r < M) {
                const __nv_bfloat16* arow = A + (size_t)(m0 + r) * 512 + kc + cl * 8;
                cp_async16(sb + 0 * TILE_B + doff, arow);        // A hi
                cp_async16(sb + 1 * TILE_B + doff, arow + 256);  // A lo
            }
            const size_t boff = (size_t)(n0 + r) * 256 + kc + cl * 8;
            cp_async16(sb + 2 * TILE_B + doff, Bhi + boff);
            cp_async16(sb + 3 * TILE_B + doff, Blo + boff);
        }
        CP_COMMIT();
    };

    load_chunk(0, 0);

    for (int c = 0; c < 8; ++c) {
        const int buf = c & 1;
        if (c < 7) {
            load_chunk(c + 1, buf ^ 1);
            CP_WAIT(1);
        } else {
            CP_WAIT(0);
        }
        __syncthreads();

        const uint32_t sb = sbase + buf * 4 * TILE_B;

#pragma unroll
        for (int ks = 0; ks < 32; ks += 16) {
            uint32_t ahi[2][4], alo[2][4], bhi[8][2], blo[8][2];
#pragma unroll
            for (int mt = 0; mt < 2; ++mt) {
                int row = wm * 32 + mt * 16 + a_row_l;
                uint32_t off = (uint32_t)(row * SLDA + ks + a_col_l) * 2;
                LDMX4(ahi[mt][0], ahi[mt][1], ahi[mt][2], ahi[mt][3],
                      sb + 0 * TILE_B + off);
                LDMX4(alo[mt][0], alo[mt][1], alo[mt][2], alo[mt][3],
                      sb + 1 * TILE_B + off);
            }
#pragma unroll
            for (int p = 0; p < 4; ++p) {
                int row = wn * 64 + p * 16 + b_row_l;
                uint32_t off = (uint32_t)(row * SLDA + ks + b_col_l) * 2;
                uint32_t r0, r1, r2, r3;
                LDMX4(r0, r1, r2, r3, sb + 2 * TILE_B + off);
                bhi[2 * p][0] = r0; bhi[2 * p][1] = r1;
                bhi[2 * p + 1][0] = r2; bhi[2 * p + 1][1] = r3;
                LDMX4(r0, r1, r2, r3, sb + 3 * TILE_B + off);
                blo[2 * p][0] = r0; blo[2 * p][1] = r1;
                blo[2 * p + 1][0] = r2; blo[2 * p + 1][1] = r3;
            }
#pragma unroll
            for (int nt = 0; nt < 8; ++nt)
#pragma unroll
                for (int mt = 0; mt < 2; ++mt) {
                    MMA16816(acc[mt][nt], ahi[mt], bhi[nt]);
                    MMA16816(acc[mt][nt], alo[mt], bhi[nt]);
                    MMA16816(acc[mt][nt], ahi[mt], blo[nt]);
                }
        }
        __syncthreads();
    }

#pragma unroll
    for (int mt = 0; mt < 2; ++mt) {
        int r0 = m0 + wm * 32 + mt * 16 + g;
#pragma unroll
        for (int nt = 0; nt < 8; ++nt) {
            int col = n0 + wn * 64 + nt * 8 + 2 * t;
            if (r0 < M)
                *(float2*)(C + (size_t)r0 * NC + col) =
                    make_float2(acc[mt][nt][0], acc[mt][nt][1]);
            if (r0 + 8 < M)
                *(float2*)(C + (size_t)(r0 + 8) * NC + col) =
                    make_float2(acc[mt][nt][2], acc[mt][nt][3]);
        }
    }
}

// ---------------------------------------------------------------------------
// Gather aggregation D=256 over node range [base, base+cnt):
// out = relu(agg + bias) as bf16 hi|lo split. Edge loop unrolled x4.
// ---------------------------------------------------------------------------
__global__ __launch_bounds__(256)
void k_gather256(const float* __restrict__ h, __nv_bfloat16* __restrict__ outs,
                 const int* __restrict__ row, const int* __restrict__ esrc,
                 const float* __restrict__ dinv, const float* __restrict__ bias,
                 int base, int cnt) {
    int node = base + ((blockIdx.x * blockDim.x + threadIdx.x) >> 5);
    int lane = threadIdx.x & 31;
    if (node >= base + cnt) return;

    float di = dinv[node];
    const float4* hp = (const float4*)h;

    float w = di * di;
    float4 v0 = hp[(size_t)node * 64 + lane];
    float4 v1 = hp[(size_t)node * 64 + lane + 32];
    float4 a0 = make_float4(v0.x * w, v0.y * w, v0.z * w, v0.w * w);
    float4 a1 = make_float4(v1.x * w, v1.y * w, v1.z * w, v1.w * w);

    int beg = row[node], end = row[node + 1];
    int e = beg;
    for (; e + 4 <= end; e += 4) {
        int s0 = esrc[e],     s1 = esrc[e + 1];
        int s2 = esrc[e + 2], s3 = esrc[e + 3];
        float nm0 = di * dinv[s0];
        float nm1 = di * dinv[s1];
        float nm2 = di * dinv[s2];
        float nm3 = di * dinv[s3];
        float4 u0 = hp[(size_t)s0 * 64 + lane];
        float4 u1 = hp[(size_t)s0 * 64 + lane + 32];
        float4 p0 = hp[(size_t)s1 * 64 + lane];
        float4 p1 = hp[(size_t)s1 * 64 + lane + 32];
        float4 q0 = hp[(size_t)s2 * 64 + lane];
        float4 q1 = hp[(size_t)s2 * 64 + lane + 32];
        float4 r0 = hp[(size_t)s3 * 64 + lane];
        float4 r1 = hp[(size_t)s3 * 64 + lane + 32];
        a0.x = fmaf(u0.x, nm0, a0.x); a0.y = fmaf(u0.y, nm0, a0.y);
        a0.z = fmaf(u0.z, nm0, a0.z); a0.w = fmaf(u0.w, nm0, a0.w);
        a1.x = fmaf(u1.x, nm0, a1.x); a1.y = fmaf(u1.y, nm0, a1.y);
        a1.z = fmaf(u1.z, nm0, a1.z); a1.w = fmaf(u1.w, nm0, a1.w);
        a0.x = fmaf(p0.x, nm1, a0.x); a0.y = fmaf(p0.y, nm1, a0.y);
        a0.z = fmaf(p0.z, nm1, a0.z); a0.w = fmaf(p0.w, nm1, a0.w);
        a1.x = fmaf(p1.x, nm1, a1.x); a1.y = fmaf(p1.y, nm1, a1.y);
        a1.z = fmaf(p1.z, nm1, a1.z); a1.w = fmaf(p1.w, nm1, a1.w);
        a0.x = fmaf(q0.x, nm2, a0.x); a0.y = fmaf(q0.y, nm2, a0.y);
        a0.z = fmaf(q0.z, nm2, a0.z); a0.w = fmaf(q0.w, nm2, a0.w);
        a1.x = fmaf(q1.x, nm2, a1.x); a1.y = fmaf(q1.y, nm2, a1.y);
        a1.z = fmaf(q1.z, nm2, a1.z); a1.w = fmaf(q1.w, nm2, a1.w);
        a0.x = fmaf(r0.x, nm3, a0.x); a0.y = fmaf(r0.y, nm3, a0.y);
        a0.z = fmaf(r0.z, nm3, a0.z); a0.w = fmaf(r0.w, nm3, a0.w);
        a1.x = fmaf(r1.x, nm3, a1.x); a1.y = fmaf(r1.y, nm3, a1.y);
        a1.z = fmaf(r1.z, nm3, a1.z); a1.w = fmaf(r1.w, nm3, a1.w);
    }
    for (; e < end; ++e) {
        int s = esrc[e];
        float nm = di * dinv[s];
        float4 u0 = hp[(size_t)s * 64 + lane];
        float4 u1 = hp[(size_t)s * 64 + lane + 32];
        a0.x = fmaf(u0.x, nm, a0.x); a0.y = fmaf(u0.y, nm, a0.y);
        a0.z = fmaf(u0.z, nm, a0.z); a0.w = fmaf(u0.w, nm, a0.w);
        a1.x = fmaf(u1.x, nm, a1.x); a1.y = fmaf(u1.y, nm, a1.y);
        a1.z = fmaf(u1.z, nm, a1.z); a1.w = fmaf(u1.w, nm, a1.w);
    }

    float4 b0 = ((const float4*)bias)[lane];
    float4 b1 = ((const float4*)bias)[lane + 32];
    a0.x = fmaxf(a0.x + b0.x, 0.f); a0.y = fmaxf(a0.y + b0.y, 0.f);
    a0.z = fmaxf(a0.z + b0.z, 0.f); a0.w = fmaxf(a0.w + b0.w, 0.f);
    a1.x = fmaxf(a1.x + b1.x, 0.f); a1.y = fmaxf(a1.y + b1.y, 0.f);
    a1.z = fmaxf(a1.z + b1.z, 0.f); a1.w = fmaxf(a1.w + b1.w, 0.f);

    __nv_bfloat16* outb = outs + (size_t)node * 512;
    split_store4(outb + lane * 4,       outb + 256 + lane * 4, a0);
    split_store4(outb + 128 + lane * 4, outb + 384 + lane * 4, a1);
}

// ---------------------------------------------------------------------------
// Gather aggregation D=128 over combined nodes: out = agg + bias (fp32,
// writes [u; v] == d_out directly)
// ---------------------------------------------------------------------------
__global__ __launch_bounds__(256)
void k_gather128(const float* __restrict__ h, float* __restrict__ out,
                 const int* __restrict__ row, const int* __restrict__ esrc,
                 const float* __restrict__ dinv, const float* __restrict__ bias) {
    int node = (blockIdx.x * blockDim.x + threadIdx.x) >> 5;
    int lane = threadIdx.x & 31;
    if (node >= TOTN) return;

    float di = dinv[node];
    const float4* hp = (const float4*)h;

    float w = di * di;
    float4 v = hp[(size_t)node * 32 + lane];
    float4 a = make_float4(v.x * w, v.y * w, v.z * w, v.w * w);

    int beg = row[node], end = row[node + 1];
    int e = beg;
    for (; e + 4 <= end; e += 4) {
        int s0 = esrc[e],     s1 = esrc[e + 1];
        int s2 = esrc[e + 2], s3 = esrc[e + 3];
        float nm0 = di * dinv[s0];
        float nm1 = di * dinv[s1];
        float nm2 = di * dinv[s2];
        float nm3 = di * dinv[s3];
        float4 u = hp[(size_t)s0 * 32 + lane];
        float4 p = hp[(size_t)s1 * 32 + lane];
        float4 q = hp[(size_t)s2 * 32 + lane];
        float4 r = hp[(size_t)s3 * 32 + lane];
        a.x = fmaf(u.x, nm0, a.x); a.y = fmaf(u.y, nm0, a.y);
        a.z = fmaf(u.z, nm0, a.z); a.w = fmaf(u.w, nm0, a.w);
        a.x = fmaf(p.x, nm1, a.x); a.y = fmaf(p.y, nm1, a.y);
        a.z = fmaf(p.z, nm1, a.z); a.w = fmaf(p.w, nm1, a.w);
        a.x = fmaf(q.x, nm2, a.x); a.y = fmaf(q.y, nm2, a.y);
        a.z = fmaf(q.z, nm2, a.z); a.w = fmaf(q.w, nm2, a.w);
        a.x = fmaf(r.x, nm3, a.x); a.y = fmaf(r.y, nm3, a.y);
        a.z = fmaf(r.z, nm3, a.z); a.w = fmaf(r.w, nm3, a.w);
    }
    for (; e < end; ++e) {
        int s = esrc[e];
        float nm = di * dinv[s];
        float4 u = hp[(size_t)s * 32 + lane];
        a.x = fmaf(u.x, nm, a.x); a.y = fmaf(u.y, nm, a.y);
        a.z = fmaf(u.z, nm, a.z); a.w = fmaf(u.w, nm, a.w);
    }

    float4 b = ((const float4*)bias)[lane];
    a.x += b.x; a.y += b.y; a.z += b.z; a.w += b.w;

    ((float4*)out)[(size_t)node * 32 + lane] = a;
}

// ---------------------------------------------------------------------------
// Host orchestration: two-level fork-join pipeline.
//   s2 @t0: cvt_x2(H1) -> CSR build -> cvt_w(W2)
//   main : cvt_w(W1) -> cvt_x2(H0) -> GEMM1(H0) -> [evX1] GEMM1(H1)
//          -> [evCSR] g256(H0) -> {evG0 -> s2: g256(H1)}
//          -> GEMM2(H0)   (overlaps g256(H1))
//          -> [evG1] GEMM2(H1) -> g128(all)
// ---------------------------------------------------------------------------
extern "C" void kernel_launch(void* const* d_in, const int* in_sizes, int n_in,
                              void* d_out, int out_size) {
    const float* x1  = (const float*)d_in[0];
    const int*   ei1 = (const int*)  d_in[1];
    const float* x2  = (const float*)d_in[2];
    const int*   ei2 = (const int*)  d_in[3];
    const float* W1  = (const float*)d_in[4];
    const float* b1  = (const float*)d_in[5];
    const float* W2  = (const float*)d_in[6];
    const float* b2  = (const float*)d_in[7];
    float* out = (float*)d_out;

    __nv_bfloat16 *xs, *aggs, *w1hi, *w1lo, *w2hi, *w2lo;
    float *h1, *h2, *dinv;
    int *count, *row, *cur, *esrc, *bsum;
    cudaGetSymbolAddress((void**)&xs,   g_xs);
    cudaGetSymbolAddress((void**)&aggs, g_aggs);
    cudaGetSymbolAddress((void**)&h1,   g_h1);
    cudaGetSymbolAddress((void**)&h2,   g_h2);
    cudaGetSymbolAddress((void**)&dinv, g_dinv);
    cudaGetSymbolAddress((void**)&count,g_count);
    cudaGetSymbolAddress((void**)&row,  g_row);
    cudaGetSymbolAddress((void**)&cur,  g_cur);
    cudaGetSymbolAddress((void**)&esrc, g_esrc);
    cudaGetSymbolAddress((void**)&bsum, g_bsum);
    cudaGetSymbolAddress((void**)&w1hi, g_w1hi);
    cudaGetSymbolAddress((void**)&w1lo, g_w1lo);
    cudaGetSymbolAddress((void**)&w2hi, g_w2hi);
    cudaGetSymbolAddress((void**)&w2lo, g_w2lo);

    cudaFuncSetAttribute(k_mma_gemm<HID_DIM>,
                         cudaFuncAttributeMaxDynamicSharedMemorySize, GSMEM);
    cudaFuncSetAttribute(k_mma_gemm<OUT_DIM>,
                         cudaFuncAttributeMaxDynamicSharedMemorySize, GSMEM);

    const int TB = 256;
    const int* src1 = ei1;
    const int* dst1 = ei1 + N_EDGES;
    const int* src2 = ei2;
    const int* dst2 = ei2 + N_EDGES;

    cudaStream_t s2;
    cudaStreamCreateWithFlags(&s2, cudaStreamNonBlocking);
    cudaEvent_t evFork, evX1, evCSR, evG0, evG1;
    cudaEventCreateWithFlags(&evFork, cudaEventDisableTiming);
    cudaEventCreateWithFlags(&evX1,   cudaEventDisableTiming);
    cudaEventCreateWithFlags(&evCSR,  cudaEventDisableTiming);
    cudaEventCreateWithFlags(&evG0,   cudaEventDisableTiming);
    cudaEventCreateWithFlags(&evG1,   cudaEventDisableTiming);

    // ---- fork ----
    cudaEventRecord(evFork, 0);
    cudaStreamWaitEvent(s2, evFork, 0);

    // side stream: xs(H1) conversion first (unblocks GEMM1(H1) early)
    k_cvt_x2<<<(H1_NODES * 64 + TB - 1) / TB, TB, 0, s2>>>(x1, x2, xs, H0_NODES, H1_NODES);
    cudaEventRecord(evX1, s2);
    // then CSR build + W2 conversion
    cudaMemsetAsync(count, 0, TOTN * sizeof(int), s2);
    k_hist2   <<<(TOTE + TB - 1) / TB, TB, 0, s2>>>(dst1, dst2, count);
    k_scan_a  <<<SNB, SBS, 0, s2>>>(count, bsum);
    k_scan_b  <<<1, 128, 0, s2>>>(bsum);
    k_scan_c  <<<SNB, SBS, 0, s2>>>(count, bsum, row, cur, dinv);
    k_scatter2<<<(TOTE + TB - 1) / TB, TB, 0, s2>>>(src1, dst1, src2, dst2, cur, esrc);
    k_cvt_w   <<<(256 * OUT_DIM + 255) / 256, 256, 0, s2>>>(W2, w2hi, w2lo, OUT_DIM);
    cudaEventRecord(evCSR, s2);

    // main stream: W1 conversion, xs(H0), GEMM1 halves
    k_cvt_w <<<(256 * HID_DIM + 255) / 256, 256>>>(W1, w1hi, w1lo, HID_DIM);
    k_cvt_x2<<<(H0_NODES * 64 + TB - 1) / TB, TB>>>(x1, x2, xs, 0, H0_NODES);
    {
        dim3 grid(H0_TILES, HID_DIM / 128);
        k_mma_gemm<HID_DIM><<<grid, 256, GSMEM>>>(xs, w1hi, w1lo, h1, TOTN, 0);
    }
    cudaStreamWaitEvent(0, evX1, 0);
    {
        dim3 grid(H1_TILES, HID_DIM / 128);
        k_mma_gemm<HID_DIM><<<grid, 256, GSMEM>>>(xs, w1hi, w1lo, h1, TOTN, H0_TILES);
    }

    // join CSR; gather half 0 on main
    cudaStreamWaitEvent(0, evCSR, 0);
    k_gather256<<<(H0_NODES + 7) / 8, TB>>>(h1, aggs, row, esrc, dinv, b1, 0, H0_NODES);
    cudaEventRecord(evG0, 0);

    // side stream: gather half 1 (overlaps GEMM2(H0) on main)
    cudaStreamWaitEvent(s2, evG0, 0);
    k_gather256<<<(H1_NODES + 7) / 8, TB, 0, s2>>>(h1, aggs, row, esrc, dinv, b1,
                                                   H0_NODES, H1_NODES);
    cudaEventRecord(evG1, s2);

    // main: GEMM2(H0) concurrent with g256(H1)
    {
        dim3 grid(H0_TILES, OUT_DIM / 128);
        k_mma_gemm<OUT_DIM><<<grid, 256, GSMEM>>>(aggs, w2hi, w2lo, h2, TOTN, 0);
    }
    cudaStreamWaitEvent(0, evG1, 0);
    {
        dim3 grid(H1_TILES, OUT_DIM / 128);
        k_mma_gemm<OUT_DIM><<<grid, 256, GSMEM>>>(aggs, w2hi, w2lo, h2, TOTN, H0_TILES);
    }
    // final: d_out = aggregate(h2) + b2
    k_gather128<<<(TOTN + 7) / 8, TB>>>(h2, out, row, esrc, dinv, b2);
}

// round 17
// speedup vs baseline: 1.0509x; 1.0509x over previous
#include <cuda_runtime.h>
#include <cuda_bf16.h>
#include <cstdint>

#define N_NODES 50000
#define N_EDGES 800000
#define IN_DIM  256
#define HID_DIM 256
#define OUT_DIM 128

#define TOTN (2 * N_NODES)   // combined node slots (both graphs)
#define TOTE (2 * N_EDGES)   // combined edges

// ---------------------------------------------------------------------------
// Device scratch (no runtime allocation allowed) — combined for both graphs
// ---------------------------------------------------------------------------
__device__ __align__(128) __nv_bfloat16 g_xs  [TOTN * 512];  // x split: [hi(256) | lo(256)]
__device__ __align__(128) __nv_bfloat16 g_aggs[TOTN * 512];  // agg split: [hi | lo]
__device__ __align__(128) float         g_h1  [TOTN * HID_DIM];
__device__ __align__(128) float         g_h2  [TOTN * OUT_DIM];
__device__ __align__(128) __nv_bfloat16 g_w1hi[HID_DIM * 256];  // [N=256][K=256] K-major
__device__ __align__(128) __nv_bfloat16 g_w1lo[HID_DIM * 256];
__device__ __align__(128) __nv_bfloat16 g_w2hi[OUT_DIM * 256];  // [N=128][K=256]
__device__ __align__(128) __nv_bfloat16 g_w2lo[OUT_DIM * 256];
__device__ float g_dinv[TOTN];
__device__ int   g_count[TOTN];
__device__ int   g_row  [TOTN + 1];
__device__ int   g_cur  [TOTN];
__device__ int   g_esrc [TOTE];      // GLOBAL source ids (graph2 offset by N_NODES)

// decomposed-scan block sums
#define SBS 1024
#define SNB ((TOTN + SBS - 1) / SBS)   // 98
__device__ int g_bsum[SNB];

// ---------------------------------------------------------------------------
// PTX helpers (all legal at base sm_103 target)
// ---------------------------------------------------------------------------
__device__ __forceinline__ uint32_t s2u(const void* p) {
    uint32_t a;
    asm("{ .reg .u64 t; cvta.to.shared.u64 t, %1; cvt.u32.u64 %0, t; }"
        : "=r"(a) : "l"(p));
    return a;
}
__device__ __forceinline__ void cp_async16(uint32_t dst, const void* src) {
    asm volatile("cp.async.cg.shared.global [%0], [%1], 16;" :: "r"(dst), "l"(src));
}
#define CP_COMMIT() asm volatile("cp.async.commit_group;" ::: "memory")
#define CP_WAIT(n)  asm volatile("cp.async.wait_group %0;" :: "n"(n) : "memory")

#define LDMX4(r0, r1, r2, r3, addr) \
    asm volatile("ldmatrix.sync.aligned.m8n8.x4.shared.b16 {%0,%1,%2,%3}, [%4];" \
                 : "=r"(r0), "=r"(r1), "=r"(r2), "=r"(r3) : "r"(addr))

#define MMA16816(d, a, b) \
    asm volatile("mma.sync.aligned.m16n8k16.row.col.f32.bf16.bf16.f32 " \
                 "{%0,%1,%2,%3}, {%4,%5,%6,%7}, {%8,%9}, {%0,%1,%2,%3};" \
                 : "+f"((d)[0]), "+f"((d)[1]), "+f"((d)[2]), "+f"((d)[3]) \
                 : "r"((a)[0]), "r"((a)[1]), "r"((a)[2]), "r"((a)[3]), \
                   "r"((b)[0]), "r"((b)[1]))

// ---------------------------------------------------------------------------
// CSR build (both graphs combined)
// ---------------------------------------------------------------------------
__global__ void k_hist2(const int* __restrict__ dst1, const int* __restrict__ dst2,
                        int* __restrict__ count) {
    int e = blockIdx.x * blockDim.x + threadIdx.x;
    if (e >= TOTE) return;
    int slot = (e < N_EDGES) ? dst1[e] : (dst2[e - N_EDGES] + N_NODES);
    atomicAdd(&count[slot], 1);
}

__global__ __launch_bounds__(SBS)
void k_scan_a(const int* __restrict__ count, int* __restrict__ bsum) {
    __shared__ int sh[SBS / 32];
    int i = blockIdx.x * SBS + threadIdx.x;
    int v = (i < TOTN) ? count[i] : 0;
#pragma unroll
    for (int off = 16; off > 0; off >>= 1)
        v += __shfl_down_sync(0xffffffff, v, off);
    if ((threadIdx.x & 31) == 0) sh[threadIdx.x >> 5] = v;
    __syncthreads();
    if (threadIdx.x < SBS / 32) {
        int s = sh[threadIdx.x];
#pragma unroll
        for (int off = SBS / 64; off > 0; off >>= 1)
            s += __shfl_down_sync(0xffffffff, s, off, SBS / 32);
        if (threadIdx.x == 0) bsum[blockIdx.x] = s;
    }
}

__global__ __launch_bounds__(128)
void k_scan_b(int* __restrict__ bsum) {
    __shared__ int sh[128];
    int tid = threadIdx.x;
    int v = (tid < SNB) ? bsum[tid] : 0;
    sh[tid] = v;
    __syncthreads();
    for (int off = 1; off < 128; off <<= 1) {
        int t = 0;
        if (tid >= off) t = sh[tid - off];
        __syncthreads();
        if (tid >= off) sh[tid] += t;
        __syncthreads();
    }
    if (tid < SNB) bsum[tid] = sh[tid] - v;   // exclusive
}

__global__ __launch_bounds__(SBS)
void k_scan_c(const int* __restrict__ count, const int* __restrict__ bsum,
              int* __restrict__ row, int* __restrict__ cur,
              float* __restrict__ dinv) {
    __shared__ int sh[SBS];
    int tid = threadIdx.x;
    int i = blockIdx.x * SBS + tid;
    int v = (i < TOTN) ? count[i] : 0;
    sh[tid] = v;
    __syncthreads();
    for (int off = 1; off < SBS; off <<= 1) {
        int t = 0;
        if (tid >= off) t = sh[tid - off];
        __syncthreads();
        if (tid >= off) sh[tid] += t;
        __syncthreads();
    }
    if (i < TOTN) {
        int excl = sh[tid] - v + bsum[blockIdx.x];
        row[i] = excl;
        cur[i] = excl;
        dinv[i] = rsqrtf((float)v + 1.0f);
        if (i == TOTN - 1) row[TOTN] = excl + v;
    }
}

__global__ void k_scatter2(const int* __restrict__ src1, const int* __restrict__ dst1,
                           const int* __restrict__ src2, const int* __restrict__ dst2,
                           int* __restrict__ cur, int* __restrict__ esrc) {
    int e = blockIdx.x * blockDim.x + threadIdx.x;
    if (e >= TOTE) return;
    int s, slot;
    if (e < N_EDGES) { s = src1[e];            slot = dst1[e]; }
    else             { s = src2[e - N_EDGES] + N_NODES;
                       slot = dst2[e - N_EDGES] + N_NODES; }
    int pos = atomicAdd(&cur[slot], 1);
    esrc[pos] = s;   // GLOBAL node id
}

// ---------------------------------------------------------------------------
// fp32 -> (hi, lo) bf16 split helpers & conversion kernels
// ---------------------------------------------------------------------------
__device__ __forceinline__ void split_store4(__nv_bfloat16* hp, __nv_bfloat16* lp, float4 v) {
    __nv_bfloat162 h01 = __floats2bfloat162_rn(v.x, v.y);
    __nv_bfloat162 h23 = __floats2bfloat162_rn(v.z, v.w);
    float2 f01 = __bfloat1622float2(h01);
    float2 f23 = __bfloat1622float2(h23);
    __nv_bfloat162 l01 = __floats2bfloat162_rn(v.x - f01.x, v.y - f01.y);
    __nv_bfloat162 l23 = __floats2bfloat162_rn(v.z - f23.x, v.w - f23.y);
    ((__nv_bfloat162*)hp)[0] = h01;
    ((__nv_bfloat162*)hp)[1] = h23;
    ((__nv_bfloat162*)lp)[0] = l01;
    ((__nv_bfloat162*)lp)[1] = l23;
}

// both graphs' x -> combined xs [TOTN, 512]
__global__ void k_cvt_x2(const float* __restrict__ x1, const float* __restrict__ x2,
                         __nv_bfloat16* __restrict__ xs) {
    int idx = blockIdx.x * blockDim.x + threadIdx.x;  // float4 index
    if (idx >= TOTN * 64) return;
    int node = idx >> 6;
    int f4   = idx & 63;
    const float4* src = (node < N_NODES)
        ? (const float4*)x1 + ((size_t)node * 64 + f4)
        : (const float4*)x2 + ((size_t)(node - N_NODES) * 64 + f4);
    float4 v = *src;
    split_store4(xs + (size_t)node * 512 + f4 * 4,
                 xs + (size_t)node * 512 + 256 + f4 * 4, v);
}

// W [K=256, N] row-major fp32 -> hi/lo [N, 256] K-major bf16 (transposed)
__global__ void k_cvt_w(const float* __restrict__ W, __nv_bfloat16* __restrict__ hi,
                        __nv_bfloat16* __restrict__ lo, int N) {
    int idx = blockIdx.x * blockDim.x + threadIdx.x;
    if (idx >= 256 * N) return;
    int n = idx / 256;
    int k = idx % 256;
    float v = W[(size_t)k * N + n];
    __nv_bfloat16 h = __float2bfloat16(v);
    hi[(size_t)n * 256 + k] = h;
    lo[(size_t)n * 256 + k] = __float2bfloat16(v - __bfloat162float(h));
}

// ---------------------------------------------------------------------------
// mma.sync bf16x3 GEMM:
//   8 K32-chunks; each chunk loads 4 tiles (Ahi, Alo, Bhi, Blo) and performs
//   all 3 split passes (Ahi*Bhi + Alo*Bhi + Ahi*Blo) with ldmatrix fragments.
// CTA: 128(M) x 128(N), 8 warps in 4(M) x 2(N); warp tile 32x64.
// ---------------------------------------------------------------------------
#define SLDA 40                       // smem row stride (bf16): 32 data + 8 pad
#define TILE_E (128 * SLDA)           // elements per tile
#define TILE_B (TILE_E * 2)           // bytes per tile (10240)
#define GSMEM  (8 * TILE_B)           // 2 buffers x 4 tiles = 81920 bytes

template <int NC>
__global__ __launch_bounds__(256)
void k_mma_gemm(const __nv_bfloat16* __restrict__ A,
                const __nv_bfloat16* __restrict__ Bhi,
                const __nv_bfloat16* __restrict__ Blo,
                float* __restrict__ C, int M) {
    extern __shared__ __align__(16) __nv_bfloat16 smem[];
    const uint32_t sbase = s2u(smem);

    const int tid  = threadIdx.x;
    const int wid  = tid >> 5;
    const int lane = tid & 31;
    const int wm   = wid & 3;        // warp M index (0..3) -> 32 rows
    const int wn   = wid >> 2;       // warp N index (0..1) -> 64 cols
    const int m0   = blockIdx.x * 128;
    const int n0   = blockIdx.y * 128;
    const int g    = lane >> 2;      // mma group row
    const int t    = lane & 3;       // mma thread col

    const int a_row_l = lane & 15;
    const int a_col_l = (lane >> 4) * 8;
    const int g8      = lane >> 3;
    const int b_row_l = (lane & 7) + 8 * (g8 >> 1);
    const int b_col_l = 8 * (g8 & 1);

    float acc[2][8][4];
#pragma unroll
    for (int i = 0; i < 2; ++i)
#pragma unroll
        for (int j = 0; j < 8; ++j)
#pragma unroll
            for (int q = 0; q < 4; ++q) acc[i][j][q] = 0.0f;

    auto load_chunk = [&](int c, int buf) {
        const int kc = c * 32;
        const uint32_t sb = sbase + buf * 4 * TILE_B;
#pragma unroll
        for (int it = 0; it < 2; ++it) {
            int idx = it * 256 + tid;
            int r = idx >> 2, cl = idx & 3;
            uint32_t doff = (r * SLDA + cl * 8) * 2;
            if (m0 + r < M) {
                const __nv_bfloat16* arow = A + (size_t)(m0 + r) * 512 + kc + cl * 8;
                cp_async16(sb + 0 * TILE_B + doff, arow);        // A hi
                cp_async16(sb + 1 * TILE_B + doff, arow + 256);  // A lo
            }
            const size_t boff = (size_t)(n0 + r) * 256 + kc + cl * 8;
            cp_async16(sb + 2 * TILE_B + doff, Bhi + boff);
            cp_async16(sb + 3 * TILE_B + doff, Blo + boff);
        }
        CP_COMMIT();
    };

    load_chunk(0, 0);

    for (int c = 0; c < 8; ++c) {
        const int buf = c & 1;
        if (c < 7) {
            load_chunk(c + 1, buf ^ 1);
            CP_WAIT(1);
        } else {
            CP_WAIT(0);
        }
        __syncthreads();

        const uint32_t sb = sbase + buf * 4 * TILE_B;

#pragma unroll
        for (int ks = 0; ks < 32; ks += 16) {
            uint32_t ahi[2][4], alo[2][4], bhi[8][2], blo[8][2];
#pragma unroll
            for (int mt = 0; mt < 2; ++mt) {
                int row = wm * 32 + mt * 16 + a_row_l;
                uint32_t off = (uint32_t)(row * SLDA + ks + a_col_l) * 2;
                LDMX4(ahi[mt][0], ahi[mt][1], ahi[mt][2], ahi[mt][3],
                      sb + 0 * TILE_B + off);
                LDMX4(alo[mt][0], alo[mt][1], alo[mt][2], alo[mt][3],
                      sb + 1 * TILE_B + off);
            }
#pragma unroll
            for (int p = 0; p < 4; ++p) {
                int row = wn * 64 + p * 16 + b_row_l;
                uint32_t off = (uint32_t)(row * SLDA + ks + b_col_l) * 2;
                uint32_t r0, r1, r2, r3;
                LDMX4(r0, r1, r2, r3, sb + 2 * TILE_B + off);
                bhi[2 * p][0] = r0; bhi[2 * p][1] = r1;
                bhi[2 * p + 1][0] = r2; bhi[2 * p + 1][1] = r3;
                LDMX4(r0, r1, r2, r3, sb + 3 * TILE_B + off);
                blo[2 * p][0] = r0; blo[2 * p][1] = r1;
                blo[2 * p + 1][0] = r2; blo[2 * p + 1][1] = r3;
            }
#pragma unroll
            for (int nt = 0; nt < 8; ++nt)
#pragma unroll
                for (int mt = 0; mt < 2; ++mt) {
                    MMA16816(acc[mt][nt], ahi[mt], bhi[nt]);
                    MMA16816(acc[mt][nt], alo[mt], bhi[nt]);
                    MMA16816(acc[mt][nt], ahi[mt], blo[nt]);
                }
        }
        __syncthreads();
    }

#pragma unroll
    for (int mt = 0; mt < 2; ++mt) {
        int r0 = m0 + wm * 32 + mt * 16 + g;
#pragma unroll
        for (int nt = 0; nt < 8; ++nt) {
            int col = n0 + wn * 64 + nt * 8 + 2 * t;
            if (r0 < M)
                *(float2*)(C + (size_t)r0 * NC + col) =
                    make_float2(acc[mt][nt][0], acc[mt][nt][1]);
            if (r0 + 8 < M)
                *(float2*)(C + (size_t)(r0 + 8) * NC + col) =
                    make_float2(acc[mt][nt][2], acc[mt][nt][3]);
        }
    }
}

// ---------------------------------------------------------------------------
// Gather aggregation D=256 over combined nodes: out = relu(agg + bias) as
// bf16 hi|lo split. Edge loop unrolled x8 (16 indep float4 gathers in flight).
// ---------------------------------------------------------------------------
__global__ __launch_bounds__(256)
void k_gather256(const float* __restrict__ h, __nv_bfloat16* __restrict__ outs,
                 const int* __restrict__ row, const int* __restrict__ esrc,
                 const float* __restrict__ dinv, const float* __restrict__ bias) {
    int node = (blockIdx.x * blockDim.x + threadIdx.x) >> 5;
    int lane = threadIdx.x & 31;
    if (node >= TOTN) return;

    float di = dinv[node];
    const float4* hp = (const float4*)h;

    float w = di * di;
    float4 v0 = hp[(size_t)node * 64 + lane];
    float4 v1 = hp[(size_t)node * 64 + lane + 32];
    float4 a0 = make_float4(v0.x * w, v0.y * w, v0.z * w, v0.w * w);
    float4 a1 = make_float4(v1.x * w, v1.y * w, v1.z * w, v1.w * w);

    int beg = row[node], end = row[node + 1];
    int e = beg;
    for (; e + 8 <= end; e += 8) {
        int s[8];
        float nm[8];
#pragma unroll
        for (int i = 0; i < 8; ++i) s[i] = esrc[e + i];
#pragma unroll
        for (int i = 0; i < 8; ++i) nm[i] = di * dinv[s[i]];
        float4 L0[8], L1[8];
#pragma unroll
        for (int i = 0; i < 8; ++i) {
            L0[i] = hp[(size_t)s[i] * 64 + lane];
            L1[i] = hp[(size_t)s[i] * 64 + lane + 32];
        }
#pragma unroll
        for (int i = 0; i < 8; ++i) {
            a0.x = fmaf(L0[i].x, nm[i], a0.x); a0.y = fmaf(L0[i].y, nm[i], a0.y);
            a0.z = fmaf(L0[i].z, nm[i], a0.z); a0.w = fmaf(L0[i].w, nm[i], a0.w);
            a1.x = fmaf(L1[i].x, nm[i], a1.x); a1.y = fmaf(L1[i].y, nm[i], a1.y);
            a1.z = fmaf(L1[i].z, nm[i], a1.z); a1.w = fmaf(L1[i].w, nm[i], a1.w);
        }
    }
    for (; e < end; ++e) {
        int s = esrc[e];
        float nm = di * dinv[s];
        float4 u0 = hp[(size_t)s * 64 + lane];
        float4 u1 = hp[(size_t)s * 64 + lane + 32];
        a0.x = fmaf(u0.x, nm, a0.x); a0.y = fmaf(u0.y, nm, a0.y);
        a0.z = fmaf(u0.z, nm, a0.z); a0.w = fmaf(u0.w, nm, a0.w);
        a1.x = fmaf(u1.x, nm, a1.x); a1.y = fmaf(u1.y, nm, a1.y);
        a1.z = fmaf(u1.z, nm, a1.z); a1.w = fmaf(u1.w, nm, a1.w);
    }

    float4 b0 = ((const float4*)bias)[lane];
    float4 b1 = ((const float4*)bias)[lane + 32];
    a0.x = fmaxf(a0.x + b0.x, 0.f); a0.y = fmaxf(a0.y + b0.y, 0.f);
    a0.z = fmaxf(a0.z + b0.z, 0.f); a0.w = fmaxf(a0.w + b0.w, 0.f);
    a1.x = fmaxf(a1.x + b1.x, 0.f); a1.y = fmaxf(a1.y + b1.y, 0.f);
    a1.z = fmaxf(a1.z + b1.z, 0.f); a1.w = fmaxf(a1.w + b1.w, 0.f);

    __nv_bfloat16* base = outs + (size_t)node * 512;
    split_store4(base + lane * 4,       base + 256 + lane * 4, a0);
    split_store4(base + 128 + lane * 4, base + 384 + lane * 4, a1);
}

// ---------------------------------------------------------------------------
// Gather aggregation D=128 over combined nodes: out = agg + bias (fp32,
// writes [u; v] == d_out directly). Edge loop unrolled x8.
// ---------------------------------------------------------------------------
__global__ __launch_bounds__(256)
void k_gather128(const float* __restrict__ h, float* __restrict__ out,
                 const int* __restrict__ row, const int* __restrict__ esrc,
                 const float* __restrict__ dinv, const float* __restrict__ bias) {
    int node = (blockIdx.x * blockDim.x + threadIdx.x) >> 5;
    int lane = threadIdx.x & 31;
    if (node >= TOTN) return;

    float di = dinv[node];
    const float4* hp = (const float4*)h;

    float w = di * di;
    float4 v = hp[(size_t)node * 32 + lane];
    float4 a = make_float4(v.x * w, v.y * w, v.z * w, v.w * w);

    int beg = row[node], end = row[node + 1];
    int e = beg;
    for (; e + 8 <= end; e += 8) {
        int s[8];
        float nm[8];
#pragma unroll
        for (int i = 0; i < 8; ++i) s[i] = esrc[e + i];
#pragma unroll
        for (int i = 0; i < 8; ++i) nm[i] = di * dinv[s[i]];
        float4 L[8];
#pragma unroll
        for (int i = 0; i < 8; ++i) L[i] = hp[(size_t)s[i] * 32 + lane];
#pragma unroll
        for (int i = 0; i < 8; ++i) {
            a.x = fmaf(L[i].x, nm[i], a.x); a.y = fmaf(L[i].y, nm[i], a.y);
            a.z = fmaf(L[i].z, nm[i], a.z); a.w = fmaf(L[i].w, nm[i], a.w);
        }
    }
    for (; e < end; ++e) {
        int s = esrc[e];
        float nm = di * dinv[s];
        float4 u = hp[(size_t)s * 32 + lane];
        a.x = fmaf(u.x, nm, a.x); a.y = fmaf(u.y, nm, a.y);
        a.z = fmaf(u.z, nm, a.z); a.w = fmaf(u.w, nm, a.w);
    }

    float4 b = ((const float4*)bias)[lane];
    a.x += b.x; a.y += b.y; a.z += b.z; a.w += b.w;

    ((float4*)out)[(size_t)node * 32 + lane] = a;
}

// ---------------------------------------------------------------------------
// Host orchestration (R15 schedule — verified best): fork-join with CSR build
// + cvt_w(W2) on a side stream, overlapped with cvt_w(W1) -> cvt_x2 -> GEMM1.
// ---------------------------------------------------------------------------
extern "C" void kernel_launch(void* const* d_in, const int* in_sizes, int n_in,
                              void* d_out, int out_size) {
    const float* x1  = (const float*)d_in[0];
    const int*   ei1 = (const int*)  d_in[1];
    const float* x2  = (const float*)d_in[2];
    const int*   ei2 = (const int*)  d_in[3];
    const float* W1  = (const float*)d_in[4];
    const float* b1  = (const float*)d_in[5];
    const float* W2  = (const float*)d_in[6];
    const float* b2  = (const float*)d_in[7];
    float* out = (float*)d_out;

    __nv_bfloat16 *xs, *aggs, *w1hi, *w1lo, *w2hi, *w2lo;
    float *h1, *h2, *dinv;
    int *count, *row, *cur, *esrc, *bsum;
    cudaGetSymbolAddress((void**)&xs,   g_xs);
    cudaGetSymbolAddress((void**)&aggs, g_aggs);
    cudaGetSymbolAddress((void**)&h1,   g_h1);
    cudaGetSymbolAddress((void**)&h2,   g_h2);
    cudaGetSymbolAddress((void**)&dinv, g_dinv);
    cudaGetSymbolAddress((void**)&count,g_count);
    cudaGetSymbolAddress((void**)&row,  g_row);
    cudaGetSymbolAddress((void**)&cur,  g_cur);
    cudaGetSymbolAddress((void**)&esrc, g_esrc);
    cudaGetSymbolAddress((void**)&bsum, g_bsum);
    cudaGetSymbolAddress((void**)&w1hi, g_w1hi);
    cudaGetSymbolAddress((void**)&w1lo, g_w1lo);
    cudaGetSymbolAddress((void**)&w2hi, g_w2hi);
    cudaGetSymbolAddress((void**)&w2lo, g_w2lo);

    cudaFuncSetAttribute(k_mma_gemm<HID_DIM>,
                         cudaFuncAttributeMaxDynamicSharedMemorySize, GSMEM);
    cudaFuncSetAttribute(k_mma_gemm<OUT_DIM>,
                         cudaFuncAttributeMaxDynamicSharedMemorySize, GSMEM);

    const int TB = 256;
    const int* src1 = ei1;
    const int* dst1 = ei1 + N_EDGES;
    const int* src2 = ei2;
    const int* dst2 = ei2 + N_EDGES;

    cudaStream_t s2;
    cudaStreamCreateWithFlags(&s2, cudaStreamNonBlocking);
    cudaEvent_t evFork, evJoin;
    cudaEventCreateWithFlags(&evFork, cudaEventDisableTiming);
    cudaEventCreateWithFlags(&evJoin, cudaEventDisableTiming);

    // fork: side stream does CSR build + W2 conversion
    cudaEventRecord(evFork, 0);
    cudaStreamWaitEvent(s2, evFork, 0);

    cudaMemsetAsync(count, 0, TOTN * sizeof(int), s2);
    k_hist2   <<<(TOTE + TB - 1) / TB, TB, 0, s2>>>(dst1, dst2, count);
    k_scan_a  <<<SNB, SBS, 0, s2>>>(count, bsum);
    k_scan_b  <<<1, 128, 0, s2>>>(bsum);
    k_scan_c  <<<SNB, SBS, 0, s2>>>(count, bsum, row, cur, dinv);
    k_scatter2<<<(TOTE + TB - 1) / TB, TB, 0, s2>>>(src1, dst1, src2, dst2, cur, esrc);
    k_cvt_w   <<<(256 * OUT_DIM + 255) / 256, 256, 0, s2>>>(W2, w2hi, w2lo, OUT_DIM);

    // main stream: W1 conversion, x conversion, GEMM1
    k_cvt_w <<<(256 * HID_DIM + 255) / 256, 256>>>(W1, w1hi, w1lo, HID_DIM);
    k_cvt_x2<<<(TOTN * 64 + TB - 1) / TB, TB>>>(x1, x2, xs);

    const int GM = (TOTN + 127) / 128;   // 782
    {
        dim3 grid(GM, HID_DIM / 128);
        k_mma_gemm<HID_DIM><<<grid, 256, GSMEM>>>(xs, w1hi, w1lo, h1, TOTN);
    }

    // join: gather needs CSR (side stream) + h1 (main stream)
    cudaEventRecord(evJoin, s2);
    cudaStreamWaitEvent(0, evJoin, 0);

    // agg = relu(aggregate(h1) + b1)
    k_gather256<<<(TOTN + 7) / 8, TB>>>(h1, aggs, row, esrc, dinv, b1);
    // layer 2: h2 = aggs @ W2
    {
        dim3 grid(GM, OUT_DIM / 128);
        k_mma_gemm<OUT_DIM><<<grid, 256, GSMEM>>>(aggs, w2hi, w2lo, h2, TOTN);
    }
    // final: d_out = aggregate(h2) + b2   ([u; v] layout matches d_out)
    k_gather128<<<(TOTN + 7) / 8, TB>>>(h2, out, row, esrc, dinv, b2);
}